// round 7
// baseline (speedup 1.0000x reference)
#include <cuda_runtime.h>
#include <cuda_bf16.h>

// Problem constants (fixed by dataset)
#define N_TIME   64
#define N_BATCH  8192
#define N_STATE  32
#define N_FORCE  16
#define DT_STEP  0.05f

#define WARPS_PER_BLOCK 4
#define THREADS_PER_BLOCK (WARPS_PER_BLOCK * 32)
#define YSTRIDE 36   // per-element smem stride in floats (144B, 16B-aligned)

typedef unsigned long long u64;

// Precomputed fu = U u_t + b for t = 1..N_TIME-1, layout [t-1][elt][h] as float2
// (states 2h, 2h+1). Static __device__ scratch (no runtime allocation).
#define FU_STEPS (N_TIME - 1)
__device__ float2 g_fu[(size_t)FU_STEPS * N_BATCH * (N_STATE / 2)];

__device__ __forceinline__ u64 fma2(u64 a, u64 b, u64 c) {
    u64 d;
    asm("fma.rn.f32x2 %0, %1, %2, %3;" : "=l"(d) : "l"(a), "l"(b), "l"(c));
    return d;
}
__device__ __forceinline__ u64 add2(u64 a, u64 b) {
    u64 d;
    asm("add.rn.f32x2 %0, %1, %2;" : "=l"(d) : "l"(a), "l"(b));
    return d;
}
__device__ __forceinline__ u64 pk2(float x, float y) {
    u64 r;
    asm("mov.b64 %0, {%1, %2};" : "=l"(r) : "f"(x), "f"(y));
    return r;
}
__device__ __forceinline__ void upk2(u64 v, float& x, float& y) {
    asm("mov.b64 {%0, %1}, %2;" : "=f"(x), "=f"(y) : "l"(v));
}

// HW tanh (MUFU, ~5e-4 abs): predictor + middle iteration only.
__device__ __forceinline__ float tanh_approx(float x) {
    float r;
    asm("tanh.approx.f32 %0, %1;" : "=f"(r) : "f"(x));
    return r;
}
// Accurate tanh (~1e-7): final iteration (sets the trajectory error floor).
__device__ __forceinline__ float tanh_exact(float x) {
    x = fminf(fmaxf(x, -9.0f), 9.0f);
    float e = __expf(2.0f * x);
    return __fdividef(e - 1.0f, e + 1.0f);
}

// y (32 floats in smem) dotted with this lane's two W rows.
// 4x LDS.128 as ulonglong2 (register pairs feed fma2 directly, zero packing movs).
__device__ __forceinline__ void matvec_rows(const float* __restrict__ buf,
                                            const u64* __restrict__ wp0,
                                            const u64* __restrict__ wp1,
                                            float& r0, float& r1)
{
    const ulonglong2* yv = (const ulonglong2*)buf;
    u64 a0a = 0ULL, a0b = 0ULL, a1a = 0ULL, a1b = 0ULL;
#pragma unroll
    for (int jv = 0; jv < N_STATE / 4; jv++) {
        ulonglong2 q = yv[jv];          // y[4jv .. 4jv+3]
        a0a = fma2(wp0[2 * jv],     q.x, a0a);
        a0b = fma2(wp0[2 * jv + 1], q.y, a0b);
        a1a = fma2(wp1[2 * jv],     q.x, a1a);
        a1b = fma2(wp1[2 * jv + 1], q.y, a1b);
    }
    u64 a0 = add2(a0a, a0b);
    u64 a1 = add2(a1a, a1b);
    float x0, y0f, x1, y1f;
    upk2(a0, x0, y0f); upk2(a1, x1, y1f);
    r0 = x0 + y0f;
    r1 = x1 + y1f;
}

// ── Pre-kernel: fu[t-1][elt][h] = (U u_t + b)[2h:2h+2].  Streaming, memory-bound. ──
__global__ __launch_bounds__(THREADS_PER_BLOCK)
void fu_kernel(const float* __restrict__ forces,
               const float* __restrict__ Umat,
               const float* __restrict__ bvec)
{
    const int wib  = threadIdx.x >> 5;
    const int lane = threadIdx.x & 31;
    const int half = lane >> 4;
    const int h    = lane & 15;
    const int s0   = 2 * h;
    const int elt  = (blockIdx.x * WARPS_PER_BLOCK + wib) * 2 + half;
    const int t    = blockIdx.y + 1;   // 1 .. N_TIME-1

    u64 up0[N_FORCE / 2], up1[N_FORCE / 2];
    const u64* U0 = (const u64*)(Umat + (size_t)s0 * N_FORCE);
    const u64* U1 = (const u64*)(Umat + (size_t)(s0 + 1) * N_FORCE);
#pragma unroll
    for (int j = 0; j < N_FORCE / 2; j++) { up0[j] = U0[j]; up1[j] = U1[j]; }

    u64 a0 = pk2(bvec[s0], 0.0f);
    u64 a1 = pk2(bvec[s0 + 1], 0.0f);
    const u64* fp = (const u64*)(forces + ((size_t)t * N_BATCH + elt) * N_FORCE);
#pragma unroll
    for (int j = 0; j < N_FORCE / 2; j++) {
        u64 uv = fp[j];
        a0 = fma2(up0[j], uv, a0);
        a1 = fma2(up1[j], uv, a1);
    }
    float l0, h0, l1, h1;
    upk2(a0, l0, h0); upk2(a1, l1, h1);
    g_fu[((size_t)(t - 1) * N_BATCH + elt) * (N_STATE / 2) + h] =
        make_float2(l0 + h0, l1 + h1);
}

// ── Main kernel: 63 sequential implicit steps, predictor + 2 Picard matvecs. ──
__global__ __launch_bounds__(THREADS_PER_BLOCK, 6)
void recsolve_kernel(const float* __restrict__ y0,
                     const float* __restrict__ Wmat,
                     float* __restrict__ out)
{
    // 2 batch elements per warp (half-warp each); lane h owns state rows 2h, 2h+1.
    __shared__ float ysh[WARPS_PER_BLOCK][2][2 * YSTRIDE];

    const int wib  = threadIdx.x >> 5;
    const int lane = threadIdx.x & 31;
    const int half = lane >> 4;
    const int h    = lane & 15;
    const int s0   = 2 * h;
    const int elt  = (blockIdx.x * WARPS_PER_BLOCK + wib) * 2 + half;

    // W rows s0, s0+1 packed along K as f32x2 pairs.
    u64 wp0[N_STATE / 2], wp1[N_STATE / 2];
    {
        const u64* W0 = (const u64*)(Wmat + (size_t)s0 * N_STATE);
        const u64* W1 = (const u64*)(Wmat + (size_t)(s0 + 1) * N_STATE);
#pragma unroll
        for (int j = 0; j < N_STATE / 2; j++) { wp0[j] = W0[j]; wp1[j] = W1[j]; }
    }

    float* buf0 = ysh[wib][0] + half * YSTRIDE;
    float* buf1 = ysh[wib][1] + half * YSTRIDE;

    float2 yp = *(const float2*)(y0 + (size_t)elt * N_STATE + s0);
    *(float2*)(out + (size_t)elt * N_STATE + s0) = yp;   // out[0] = y0

    // Prologue: carried z = W * y0 (exact).
    float z0, z1;
    *(float2*)(buf0 + s0) = yp;
    __syncwarp();
    matvec_rows(buf0, wp0, wp1, z0, z1);
    __syncwarp();   // all lanes done reading buf0 before t=1 overwrites it

    const u64* fu_base = (const u64*)g_fu + (size_t)elt * (N_STATE / 2) + h;
    u64 fu_bits = fu_base[0];   // t=1 slot

    for (int t = 1; t < N_TIME; t++) {
        // Prefetch next step's fu (clamped; one-step-ahead hides LDG latency).
        const int tn = (t < N_TIME - 1) ? t : t - 1;   // slot index (t+1)-1, clamped
        u64 fu_next = fu_base[(size_t)tn * N_BATCH * (N_STATE / 2)];

        float fu0, fu1;
        upk2(fu_bits, fu0, fu1);

        // Free predictor from carried z = W*y_prev (exact): Picard iterate 0.
        float yg0 = fmaf(DT_STEP, tanh_approx(z0 + fu0), yp.x);
        float yg1 = fmaf(DT_STEP, tanh_approx(z1 + fu1), yp.y);

        // Iteration 1 (matvec + approx tanh).
        *(float2*)(buf0 + s0) = make_float2(yg0, yg1);
        __syncwarp();
        float g0, g1;
        matvec_rows(buf0, wp0, wp1, g0, g1);
        float y10 = fmaf(DT_STEP, tanh_approx(g0 + fu0), yp.x);
        float y11 = fmaf(DT_STEP, tanh_approx(g1 + fu1), yp.y);

        // Iteration 2 (matvec + exact tanh); matvec result carried as z.
        *(float2*)(buf1 + s0) = make_float2(y10, y11);
        __syncwarp();
        matvec_rows(buf1, wp0, wp1, z0, z1);
        yp.x = fmaf(DT_STEP, tanh_exact(z0 + fu0), yp.x);
        yp.y = fmaf(DT_STEP, tanh_exact(z1 + fu1), yp.y);

        *(float2*)(out + ((size_t)t * N_BATCH + elt) * N_STATE + s0) = yp;
        fu_bits = fu_next;
    }
}

extern "C" void kernel_launch(void* const* d_in, const int* in_sizes, int n_in,
                              void* d_out, int out_size)
{
    const float* y0     = (const float*)d_in[0];
    const float* forces = (const float*)d_in[1];
    const float* W      = (const float*)d_in[2];
    const float* U      = (const float*)d_in[3];
    const float* b      = (const float*)d_in[4];
    float* out = (float*)d_out;

    // Phase 1: fu = U u_t + b for all (t, elt), t = 1..63.
    dim3 fgrid(N_BATCH / (WARPS_PER_BLOCK * 2), FU_STEPS);
    fu_kernel<<<fgrid, THREADS_PER_BLOCK>>>(forces, U, b);

    // Phase 2: sequential solve. 1024 blocks x 4 warps x 2 elems = 8192.
    dim3 grid(N_BATCH / (WARPS_PER_BLOCK * 2));
    recsolve_kernel<<<grid, THREADS_PER_BLOCK>>>(y0, W, out);
}

// round 10
// speedup vs baseline: 3.5352x; 3.5352x over previous
#include <cuda_runtime.h>
#include <cuda_bf16.h>

// Problem constants (fixed by dataset)
#define N_TIME   64
#define N_BATCH  8192
#define N_STATE  32
#define N_FORCE  16
#define DT_STEP  0.05f

#define WARPS_PER_BLOCK 4
#define THREADS_PER_BLOCK (WARPS_PER_BLOCK * 32)
#define YSTRIDE 36   // per-element smem stride in floats (144B, 16B-aligned)

// fu pre-pass launch shape: few big blocks, grid-stride over time.
#define FU_WARPS 8
#define FU_THREADS (FU_WARPS * 32)

typedef unsigned long long u64;

// Precomputed fu = U u_t + b for t = 1..N_TIME-1, layout [t-1][elt][h] as float2
// (states 2h, 2h+1). Static __device__ scratch (no runtime allocation).
#define FU_STEPS (N_TIME - 1)
__device__ float2 g_fu[(size_t)FU_STEPS * N_BATCH * (N_STATE / 2)];

__device__ __forceinline__ u64 fma2(u64 a, u64 b, u64 c) {
    u64 d;
    asm("fma.rn.f32x2 %0, %1, %2, %3;" : "=l"(d) : "l"(a), "l"(b), "l"(c));
    return d;
}
__device__ __forceinline__ u64 add2(u64 a, u64 b) {
    u64 d;
    asm("add.rn.f32x2 %0, %1, %2;" : "=l"(d) : "l"(a), "l"(b));
    return d;
}
__device__ __forceinline__ u64 pk2(float x, float y) {
    u64 r;
    asm("mov.b64 %0, {%1, %2};" : "=l"(r) : "f"(x), "f"(y));
    return r;
}
__device__ __forceinline__ void upk2(u64 v, float& x, float& y) {
    asm("mov.b64 {%0, %1}, %2;" : "=f"(x), "=f"(y) : "l"(v));
}

// HW tanh (MUFU, ~5e-4 abs): predictor + middle iteration only.
__device__ __forceinline__ float tanh_approx(float x) {
    float r;
    asm("tanh.approx.f32 %0, %1;" : "=f"(r) : "f"(x));
    return r;
}
// Accurate tanh (~1e-7): final iteration (sets the trajectory error floor).
__device__ __forceinline__ float tanh_exact(float x) {
    x = fminf(fmaxf(x, -9.0f), 9.0f);
    float e = __expf(2.0f * x);
    return __fdividef(e - 1.0f, e + 1.0f);
}

// y (32 floats in smem) dotted with this lane's two W rows.
// 4x LDS.128 as ulonglong2 (register pairs feed fma2 directly, zero packing movs).
__device__ __forceinline__ void matvec_rows(const float* __restrict__ buf,
                                            const u64* __restrict__ wp0,
                                            const u64* __restrict__ wp1,
                                            float& r0, float& r1)
{
    const ulonglong2* yv = (const ulonglong2*)buf;
    u64 a0a = 0ULL, a0b = 0ULL, a1a = 0ULL, a1b = 0ULL;
#pragma unroll
    for (int jv = 0; jv < N_STATE / 4; jv++) {
        ulonglong2 q = yv[jv];          // y[4jv .. 4jv+3]
        a0a = fma2(wp0[2 * jv],     q.x, a0a);
        a0b = fma2(wp0[2 * jv + 1], q.y, a0b);
        a1a = fma2(wp1[2 * jv],     q.x, a1a);
        a1b = fma2(wp1[2 * jv + 1], q.y, a1b);
    }
    u64 a0 = add2(a0a, a0b);
    u64 a1 = add2(a1a, a1b);
    float x0, y0f, x1, y1f;
    upk2(a0, x0, y0f); upk2(a1, x1, y1f);
    r0 = x0 + y0f;
    r1 = x1 + y1f;
}

// ── Pre-pass: fu[t-1][elt][h] = (U u_t + b)[2h:2h+2].
// 512 blocks x 256 threads; each warp owns 2 elements and loops over all t
// (U rows stay in registers; pure streaming — avoids the 64k-tiny-block
// launch-overhead wall the per-(t,block) grid hit).
__global__ __launch_bounds__(FU_THREADS)
void fu_kernel(const float* __restrict__ forces,
               const float* __restrict__ Umat,
               const float* __restrict__ bvec)
{
    const int wib  = threadIdx.x >> 5;
    const int lane = threadIdx.x & 31;
    const int half = lane >> 4;
    const int h    = lane & 15;
    const int s0   = 2 * h;
    const int elt  = (blockIdx.x * FU_WARPS + wib) * 2 + half;

    u64 up0[N_FORCE / 2], up1[N_FORCE / 2];
    const u64* U0 = (const u64*)(Umat + (size_t)s0 * N_FORCE);
    const u64* U1 = (const u64*)(Umat + (size_t)(s0 + 1) * N_FORCE);
#pragma unroll
    for (int j = 0; j < N_FORCE / 2; j++) { up0[j] = U0[j]; up1[j] = U1[j]; }
    const u64 bb0 = pk2(bvec[s0], 0.0f);
    const u64 bb1 = pk2(bvec[s0 + 1], 0.0f);

    const u64* fp  = (const u64*)(forces + ((size_t)1 * N_BATCH + elt) * N_FORCE);
    float2* outp   = g_fu + (size_t)elt * (N_STATE / 2) + h;
    const size_t fstride = (size_t)N_BATCH * N_FORCE / 2;        // u64 units per t
    const size_t ostride = (size_t)N_BATCH * (N_STATE / 2);      // float2 units per t

#pragma unroll 2
    for (int t = 1; t < N_TIME; t++) {
        u64 a0 = bb0, a1 = bb1;
#pragma unroll
        for (int j = 0; j < N_FORCE / 2; j++) {
            u64 uv = fp[j];
            a0 = fma2(up0[j], uv, a0);
            a1 = fma2(up1[j], uv, a1);
        }
        float l0, h0, l1, h1;
        upk2(a0, l0, h0); upk2(a1, l1, h1);
        *outp = make_float2(l0 + h0, l1 + h1);
        fp   += fstride;
        outp += ostride;
    }
}

// ── Main kernel: 63 sequential implicit steps, predictor + 2 Picard matvecs.
// (Byte-identical logic to the R7 version measured at 116.5 us.) ──
__global__ __launch_bounds__(THREADS_PER_BLOCK, 6)
void recsolve_kernel(const float* __restrict__ y0,
                     const float* __restrict__ Wmat,
                     float* __restrict__ out)
{
    // 2 batch elements per warp (half-warp each); lane h owns state rows 2h, 2h+1.
    __shared__ float ysh[WARPS_PER_BLOCK][2][2 * YSTRIDE];

    const int wib  = threadIdx.x >> 5;
    const int lane = threadIdx.x & 31;
    const int half = lane >> 4;
    const int h    = lane & 15;
    const int s0   = 2 * h;
    const int elt  = (blockIdx.x * WARPS_PER_BLOCK + wib) * 2 + half;

    // W rows s0, s0+1 packed along K as f32x2 pairs.
    u64 wp0[N_STATE / 2], wp1[N_STATE / 2];
    {
        const u64* W0 = (const u64*)(Wmat + (size_t)s0 * N_STATE);
        const u64* W1 = (const u64*)(Wmat + (size_t)(s0 + 1) * N_STATE);
#pragma unroll
        for (int j = 0; j < N_STATE / 2; j++) { wp0[j] = W0[j]; wp1[j] = W1[j]; }
    }

    float* buf0 = ysh[wib][0] + half * YSTRIDE;
    float* buf1 = ysh[wib][1] + half * YSTRIDE;

    float2 yp = *(const float2*)(y0 + (size_t)elt * N_STATE + s0);
    *(float2*)(out + (size_t)elt * N_STATE + s0) = yp;   // out[0] = y0

    // Prologue: carried z = W * y0 (exact).
    float z0, z1;
    *(float2*)(buf0 + s0) = yp;
    __syncwarp();
    matvec_rows(buf0, wp0, wp1, z0, z1);
    __syncwarp();   // all lanes done reading buf0 before t=1 overwrites it

    const u64* fu_base = (const u64*)g_fu + (size_t)elt * (N_STATE / 2) + h;
    u64 fu_bits = fu_base[0];   // t=1 slot

    for (int t = 1; t < N_TIME; t++) {
        // Prefetch next step's fu (clamped; one-step-ahead hides LDG latency).
        const int tn = (t < N_TIME - 1) ? t : t - 1;   // slot index (t+1)-1, clamped
        u64 fu_next = fu_base[(size_t)tn * N_BATCH * (N_STATE / 2)];

        float fu0, fu1;
        upk2(fu_bits, fu0, fu1);

        // Free predictor from carried z = W*y_prev (exact): Picard iterate 0.
        float yg0 = fmaf(DT_STEP, tanh_approx(z0 + fu0), yp.x);
        float yg1 = fmaf(DT_STEP, tanh_approx(z1 + fu1), yp.y);

        // Iteration 1 (matvec + approx tanh).
        *(float2*)(buf0 + s0) = make_float2(yg0, yg1);
        __syncwarp();
        float g0, g1;
        matvec_rows(buf0, wp0, wp1, g0, g1);
        float y10 = fmaf(DT_STEP, tanh_approx(g0 + fu0), yp.x);
        float y11 = fmaf(DT_STEP, tanh_approx(g1 + fu1), yp.y);

        // Iteration 2 (matvec + exact tanh); matvec result carried as z.
        *(float2*)(buf1 + s0) = make_float2(y10, y11);
        __syncwarp();
        matvec_rows(buf1, wp0, wp1, z0, z1);
        yp.x = fmaf(DT_STEP, tanh_exact(z0 + fu0), yp.x);
        yp.y = fmaf(DT_STEP, tanh_exact(z1 + fu1), yp.y);

        *(float2*)(out + ((size_t)t * N_BATCH + elt) * N_STATE + s0) = yp;
        fu_bits = fu_next;
    }
}

extern "C" void kernel_launch(void* const* d_in, const int* in_sizes, int n_in,
                              void* d_out, int out_size)
{
    const float* y0     = (const float*)d_in[0];
    const float* forces = (const float*)d_in[1];
    const float* W      = (const float*)d_in[2];
    const float* U      = (const float*)d_in[3];
    const float* b      = (const float*)d_in[4];
    float* out = (float*)d_out;

    // Phase 1: fu = U u_t + b, t = 1..63. 512 blocks x 256 threads, t-loop inside.
    dim3 fgrid(N_BATCH / (FU_WARPS * 2));
    fu_kernel<<<fgrid, FU_THREADS>>>(forces, U, b);

    // Phase 2: sequential solve. 1024 blocks x 4 warps x 2 elems = 8192.
    dim3 grid(N_BATCH / (WARPS_PER_BLOCK * 2));
    recsolve_kernel<<<grid, THREADS_PER_BLOCK>>>(y0, W, out);
}

// round 14
// speedup vs baseline: 4.5307x; 1.2816x over previous
#include <cuda_runtime.h>
#include <cuda_bf16.h>

// Problem constants (fixed by dataset)
#define N_TIME   64
#define N_BATCH  8192
#define N_STATE  32
#define N_FORCE  16
#define DT_STEP  0.05f

#define WARPS_PER_BLOCK 4
#define THREADS_PER_BLOCK (WARPS_PER_BLOCK * 32)

typedef unsigned long long u64;

// Precomputed fu = U u_t + b for t = 1..63, layout [t-1][elt][state] (float).
// Written by each warp's prologue for its own elements, read back via L2.
#define FU_STEPS (N_TIME - 1)
__device__ float g_fu[(size_t)FU_STEPS * N_BATCH * N_STATE];

__device__ __forceinline__ u64 fma2(u64 a, u64 b, u64 c) {
    u64 d;
    asm("fma.rn.f32x2 %0, %1, %2, %3;" : "=l"(d) : "l"(a), "l"(b), "l"(c));
    return d;
}
__device__ __forceinline__ u64 add2(u64 a, u64 b) {
    u64 d;
    asm("add.rn.f32x2 %0, %1, %2;" : "=l"(d) : "l"(a), "l"(b));
    return d;
}
__device__ __forceinline__ u64 pk2(float x, float y) {
    u64 r;
    asm("mov.b64 %0, {%1, %2};" : "=l"(r) : "f"(x), "f"(y));
    return r;
}
__device__ __forceinline__ void upk2(u64 v, float& x, float& y) {
    asm("mov.b64 {%0, %1}, %2;" : "=f"(x), "=f"(y) : "l"(v));
}

// HW tanh (MUFU, ~5e-4 abs): predictor + middle iteration only.
__device__ __forceinline__ float tanh_approx(float x) {
    float r;
    asm("tanh.approx.f32 %0, %1;" : "=f"(r) : "f"(x));
    return r;
}
// Accurate tanh (~1e-7): final iteration (sets the trajectory error floor).
__device__ __forceinline__ float tanh_exact(float x) {
    x = fminf(fmaxf(x, -9.0f), 9.0f);
    float e = __expf(2.0f * x);
    return __fdividef(e - 1.0f, e + 1.0f);
}

// Dot of this lane's FULL W row (16 f32x2 regs = 32 coeffs) with y (32 floats
// in smem). 8 broadcast LDS.128; result is y_next[lane] directly.
__device__ __forceinline__ float matvec_row(const float* __restrict__ buf,
                                            const u64* __restrict__ wl)
{
    const ulonglong2* yv = (const ulonglong2*)buf;
    u64 a = 0ULL, b = 0ULL;
#pragma unroll
    for (int jv = 0; jv < N_STATE / 4; jv++) {      // 8 iters: y[0..31], wl[0..15]
        ulonglong2 q = yv[jv];                      // y[4jv .. 4jv+3]
        a = fma2(wl[2 * jv],     q.x, a);
        b = fma2(wl[2 * jv + 1], q.y, b);
    }
    u64 s = add2(a, b);
    float lo, hi;
    upk2(s, lo, hi);
    return lo + hi;
}

// ── Fused kernel: fu prologue (per-warp, own elements) + 63 sequential
// implicit steps with predictor + 2 Picard matvecs.
// Lane l owns W row l and serves both of the warp's 2 elements.
// __launch_bounds__(128,7): 7 CTAs/SM -> 1036 concurrent blocks >= grid 1024
// -> SINGLE WAVE. ──
__global__ __launch_bounds__(THREADS_PER_BLOCK, 7)
void recsolve_kernel(const float* __restrict__ y0,
                     const float* __restrict__ forces,
                     const float* __restrict__ Wmat,
                     const float* __restrict__ Umat,
                     const float* __restrict__ bvec,
                     float* __restrict__ out)
{
    // Per warp: 4 buffers of 32 floats (elemA/elemB x double-buffer). Broadcast-only.
    __shared__ __align__(16) float ysh[WARPS_PER_BLOCK][4][N_STATE];

    const int wib  = threadIdx.x >> 5;
    const int lane = threadIdx.x & 31;
    const int elt0 = (blockIdx.x * WARPS_PER_BLOCK + wib) * 2;
    const int elt1 = elt0 + 1;

    const float bl = bvec[lane];

    // ── Prologue: fu[t][elt][lane] = b[lane] + U_row_lane . u_t for own 2 elems. ──
    {
        u64 ul[N_FORCE / 2];                      // U row lane: 16 floats as 8 f32x2
        const ulonglong2* Up = (const ulonglong2*)(Umat + (size_t)lane * N_FORCE);
#pragma unroll
        for (int j = 0; j < 4; j++) { ulonglong2 q = Up[j]; ul[2*j] = q.x; ul[2*j+1] = q.y; }

        float* fuout = g_fu + (size_t)elt0 * N_STATE + lane;
#pragma unroll 2
        for (int t = 1; t < N_TIME; t++) {
#pragma unroll
            for (int e = 0; e < 2; e++) {
                const ulonglong2* fp =
                    (const ulonglong2*)(forces + ((size_t)t * N_BATCH + elt0 + e) * N_FORCE);
                ulonglong2 q0 = fp[0], q1 = fp[1], q2 = fp[2], q3 = fp[3];
                u64 a = pk2(bl, 0.0f);
                a = fma2(ul[0], q0.x, a);
                a = fma2(ul[1], q0.y, a);
                a = fma2(ul[2], q1.x, a);
                a = fma2(ul[3], q1.y, a);
                a = fma2(ul[4], q2.x, a);
                a = fma2(ul[5], q2.y, a);
                a = fma2(ul[6], q3.x, a);
                a = fma2(ul[7], q3.y, a);
                float lo, hi;
                upk2(a, lo, hi);
                fuout[(size_t)(t - 1) * (N_BATCH * N_STATE) + e * N_STATE] = lo + hi;
            }
        }
    }

    // ── W row for this lane, packed along K as f32x2 pairs (16 u64 regs). ──
    u64 wl[N_STATE / 2];
    {
        const ulonglong2* Wp = (const ulonglong2*)(Wmat + (size_t)lane * N_STATE);
#pragma unroll
        for (int j = 0; j < 8; j++) { ulonglong2 q = Wp[j]; wl[2*j] = q.x; wl[2*j+1] = q.y; }
    }

    float* bufA0 = ysh[wib][0];
    float* bufB0 = ysh[wib][1];
    float* bufA1 = ysh[wib][2];
    float* bufB1 = ysh[wib][3];

    float yA = y0[(size_t)elt0 * N_STATE + lane];
    float yB = y0[(size_t)elt1 * N_STATE + lane];
    out[(size_t)elt0 * N_STATE + lane] = yA;     // out[0] = y0
    out[(size_t)elt1 * N_STATE + lane] = yB;

    // Carried z = W * y0 (exact).
    bufA0[lane] = yA;
    bufB0[lane] = yB;
    __syncwarp();
    float zA = matvec_row(bufA0, wl);
    float zB = matvec_row(bufB0, wl);
    __syncwarp();   // all lanes done reading buf*0 before t=1 overwrites

    const float* fuP = g_fu + (size_t)elt0 * N_STATE + lane;  // slot (t-1)=0
    const size_t fustride = (size_t)N_BATCH * N_STATE;
    float fuA = fuP[0];
    float fuB = fuP[N_STATE];

    for (int t = 1; t < N_TIME; t++) {
        // One-step-ahead prefetch of fu (L2-resident; clamped at the end).
        const int tn = (t < N_TIME - 1) ? t : t - 1;
        float fuA_n = fuP[(size_t)tn * fustride];
        float fuB_n = fuP[(size_t)tn * fustride + N_STATE];

        // Free predictor from carried z = W*y_prev (exact): Picard iterate 0.
        float ygA = fmaf(DT_STEP, tanh_approx(zA + fuA), yA);
        float ygB = fmaf(DT_STEP, tanh_approx(zB + fuB), yB);

        // Iteration 1 (matvec + approx tanh).
        bufA0[lane] = ygA;
        bufB0[lane] = ygB;
        __syncwarp();
        float gA = matvec_row(bufA0, wl);
        float gB = matvec_row(bufB0, wl);
        float y1A = fmaf(DT_STEP, tanh_approx(gA + fuA), yA);
        float y1B = fmaf(DT_STEP, tanh_approx(gB + fuB), yB);

        // Iteration 2 (matvec + exact tanh); matvec result carried as z.
        bufA1[lane] = y1A;
        bufB1[lane] = y1B;
        __syncwarp();
        zA = matvec_row(bufA1, wl);
        zB = matvec_row(bufB1, wl);
        yA = fmaf(DT_STEP, tanh_exact(zA + fuA), yA);
        yB = fmaf(DT_STEP, tanh_exact(zB + fuB), yB);

        out[((size_t)t * N_BATCH + elt0) * N_STATE + lane] = yA;
        out[((size_t)t * N_BATCH + elt1) * N_STATE + lane] = yB;
        fuA = fuA_n;
        fuB = fuB_n;
    }
}

extern "C" void kernel_launch(void* const* d_in, const int* in_sizes, int n_in,
                              void* d_out, int out_size)
{
    const float* y0     = (const float*)d_in[0];
    const float* forces = (const float*)d_in[1];
    const float* W      = (const float*)d_in[2];
    const float* U      = (const float*)d_in[3];
    const float* b      = (const float*)d_in[4];
    float* out = (float*)d_out;

    // 1024 blocks x 4 warps x 2 elems = 8192 elements; single wave at 7 CTAs/SM.
    dim3 grid(N_BATCH / (WARPS_PER_BLOCK * 2));
    recsolve_kernel<<<grid, THREADS_PER_BLOCK>>>(y0, forces, W, U, b, out);
}